// round 1
// baseline (speedup 1.0000x reference)
#include <cuda_runtime.h>
#include <cuda_bf16.h>
#include <stdint.h>

// Problem constants
#define K_CB   4096      // codebook entries
#define HID    1024
#define VQd    64
#define Dd     768
#define Bb     8
#define Tt     2048
#define NTOK   (Bb*Tt)   // 16384
#define L2b    12
#define N_MID  4
#define EPS_N  1e-6f
#define EPS_BN 1e-5f

// ---------------- scratch (device globals; no allocation allowed) ----------------
__device__ float g_x[K_CB * HID];        // MLP activations (ping)
__device__ float g_y[K_CB * HID];        // MLP pre-activations (pong) / raw embed
__device__ float g_embed[K_CB * VQd];    // normalized codebook
__device__ float g_enorm2[K_CB];         // ||e||^2 after normalization
__device__ float g_h[NTOK * VQd];        // normalized projected hidden states
__device__ float g_esel[NTOK * VQd];     // gathered (masked) codebook rows
__device__ float g_stats[2 * HID];       // per-feature sum / sumsq for BN
__device__ unsigned long long g_best[NTOK]; // packed (score, ~idx) argmax keys

// ---------------- small utility kernels ----------------
__global__ void zero_stats_kernel() {
    int i = blockIdx.x * 256 + threadIdx.x;
    if (i < 2 * HID) g_stats[i] = 0.f;
}
__global__ void zero_best_kernel() {
    int i = blockIdx.x * 256 + threadIdx.x;
    if (i < NTOK) g_best[i] = 0ull;
}

// ---------------- layer 0: bits @ W_in^T + b, BN (closed-form stats), ReLU ----------------
// Over all 4096 codes the bit columns are exactly iid Bernoulli(0.5):
//   mean_f = b_f + 0.5 * sum_j W[f,j];  var_f = 0.25 * sum_j W[f,j]^2   (biased, exact)
__global__ __launch_bounds__(256) void layer0_kernel(
    const float* __restrict__ W, const float* __restrict__ bias,
    const float* __restrict__ gamma, const float* __restrict__ beta,
    float* __restrict__ X)
{
    int f = blockIdx.x * 256 + threadIdx.x;     // grid.x = HID/256 = 4
    int k0 = blockIdx.y * 16;                    // grid.y = K_CB/16 = 256
    float w[L2b];
    float sw = 0.f, sw2 = 0.f;
#pragma unroll
    for (int j = 0; j < L2b; j++) {
        w[j] = W[f * L2b + j];
        sw += w[j];
        sw2 += w[j] * w[j];
    }
    float b = bias[f];
    float m = b + 0.5f * sw;
    float v = 0.25f * sw2;
    float rstd = rsqrtf(v + EPS_BN);
    float ga = gamma[f] * rstd;
    float be = beta[f];
#pragma unroll 4
    for (int kk = 0; kk < 16; kk++) {
        int k = k0 + kk;
        float y = b;
#pragma unroll
        for (int j = 0; j < L2b; j++)
            if ((k >> (11 - j)) & 1) y += w[j];
        float o = (y - m) * ga + be;
        X[k * HID + f] = fmaxf(o, 0.f);
    }
}

// ---------------- generic fp32 NT GEMM: C[m,n] = sum_k A[m,k]*B[n,k] + bias[n] ----------------
// BM=128, BN=128, BK=8, 256 threads, 8x8 register tile, conflict-free LDS.128 fragments.
__global__ __launch_bounds__(256, 2) void gemm128_nt(
    const float* __restrict__ A, const float* __restrict__ B,
    const float* __restrict__ bias, float* __restrict__ C,
    int M, int N, int K)
{
    __shared__ float As[8][132];
    __shared__ float Bs[8][132];
    const int tid = threadIdx.x;
    const int tx = tid & 15, ty = tid >> 4;
    const int m0 = blockIdx.y * 128, n0 = blockIdx.x * 128;
    const int lr = tid >> 1;            // 0..127
    const int lc = (tid & 1) << 2;      // 0 or 4
    const float* Ag = A + (size_t)(m0 + lr) * K + lc;
    const float* Bg = B + (size_t)(n0 + lr) * K + lc;

    float acc[8][8];
#pragma unroll
    for (int i = 0; i < 8; i++)
#pragma unroll
        for (int j = 0; j < 8; j++) acc[i][j] = 0.f;

    for (int k0 = 0; k0 < K; k0 += 8) {
        float4 a4 = *(const float4*)(Ag + k0);
        float4 b4 = *(const float4*)(Bg + k0);
        As[lc + 0][lr] = a4.x; As[lc + 1][lr] = a4.y; As[lc + 2][lr] = a4.z; As[lc + 3][lr] = a4.w;
        Bs[lc + 0][lr] = b4.x; Bs[lc + 1][lr] = b4.y; Bs[lc + 2][lr] = b4.z; Bs[lc + 3][lr] = b4.w;
        __syncthreads();
#pragma unroll
        for (int kk = 0; kk < 8; kk++) {
            float ar[8], br[8];
            *(float4*)&ar[0] = *(const float4*)&As[kk][ty * 4];
            *(float4*)&ar[4] = *(const float4*)&As[kk][64 + ty * 4];
            *(float4*)&br[0] = *(const float4*)&Bs[kk][tx * 4];
            *(float4*)&br[4] = *(const float4*)&Bs[kk][64 + tx * 4];
#pragma unroll
            for (int i = 0; i < 8; i++)
#pragma unroll
                for (int j = 0; j < 8; j++)
                    acc[i][j] = fmaf(ar[i], br[j], acc[i][j]);
        }
        __syncthreads();
    }
#pragma unroll
    for (int ih = 0; ih < 2; ih++) {
#pragma unroll
        for (int i = 0; i < 4; i++) {
            int r = m0 + ih * 64 + ty * 4 + i;
            float* Crow = C + (size_t)r * N + n0;
#pragma unroll
            for (int jh = 0; jh < 2; jh++) {
                int cb = jh * 64 + tx * 4;
                float4 v;
                v.x = acc[ih * 4 + i][jh * 4 + 0] + bias[n0 + cb + 0];
                v.y = acc[ih * 4 + i][jh * 4 + 1] + bias[n0 + cb + 1];
                v.z = acc[ih * 4 + i][jh * 4 + 2] + bias[n0 + cb + 2];
                v.w = acc[ih * 4 + i][jh * 4 + 3] + bias[n0 + cb + 3];
                *(float4*)(Crow + cb) = v;
            }
        }
    }
}

// ---------------- 64x64 NT GEMM (output layer, N=64) ----------------
__global__ __launch_bounds__(256) void gemm64_nt(
    const float* __restrict__ A, const float* __restrict__ B,
    const float* __restrict__ bias, float* __restrict__ C,
    int M, int N, int K)
{
    __shared__ float As[8][68];
    __shared__ float Bs[8][68];
    const int tid = threadIdx.x;
    const int tx = tid & 15, ty = tid >> 4;
    const int m0 = blockIdx.y * 64, n0 = blockIdx.x * 64;
    float acc[4][4];
#pragma unroll
    for (int i = 0; i < 4; i++)
#pragma unroll
        for (int j = 0; j < 4; j++) acc[i][j] = 0.f;

    const int half = tid >> 7;              // 0 -> A, 1 -> B
    const int lt = tid & 127;
    const int lr = lt >> 1;                 // 0..63
    const int lcv = (lt & 1) << 2;          // 0 or 4
    const float* G = half ? (B + (size_t)(n0 + lr) * K + lcv)
                          : (A + (size_t)(m0 + lr) * K + lcv);

    for (int k0 = 0; k0 < K; k0 += 8) {
        float4 g4 = *(const float4*)(G + k0);
        if (half == 0) {
            As[lcv + 0][lr] = g4.x; As[lcv + 1][lr] = g4.y; As[lcv + 2][lr] = g4.z; As[lcv + 3][lr] = g4.w;
        } else {
            Bs[lcv + 0][lr] = g4.x; Bs[lcv + 1][lr] = g4.y; Bs[lcv + 2][lr] = g4.z; Bs[lcv + 3][lr] = g4.w;
        }
        __syncthreads();
#pragma unroll
        for (int kk = 0; kk < 8; kk++) {
            float ar[4], br[4];
            *(float4*)&ar[0] = *(const float4*)&As[kk][ty * 4];
            *(float4*)&br[0] = *(const float4*)&Bs[kk][tx * 4];
#pragma unroll
            for (int i = 0; i < 4; i++)
#pragma unroll
                for (int j = 0; j < 4; j++)
                    acc[i][j] = fmaf(ar[i], br[j], acc[i][j]);
        }
        __syncthreads();
    }
#pragma unroll
    for (int i = 0; i < 4; i++) {
        int r = m0 + ty * 4 + i;
        float4 v;
        v.x = acc[i][0] + bias[n0 + tx * 4 + 0];
        v.y = acc[i][1] + bias[n0 + tx * 4 + 1];
        v.z = acc[i][2] + bias[n0 + tx * 4 + 2];
        v.w = acc[i][3] + bias[n0 + tx * 4 + 3];
        *(float4*)(C + (size_t)r * N + n0 + tx * 4) = v;
    }
}

// ---------------- BN stats over rows (sum, sumsq per feature) ----------------
__global__ __launch_bounds__(256) void bn_stats_kernel(const float* __restrict__ Y)
{
    __shared__ float ss[256], ss2[256];
    int tid = threadIdx.x;
    int f = blockIdx.x * 32 + (tid & 31);
    int r0 = blockIdx.y * 128;
    float s = 0.f, s2 = 0.f;
    for (int r = tid >> 5; r < 128; r += 8) {
        float v = Y[(size_t)(r0 + r) * HID + f];
        s += v; s2 += v * v;
    }
    ss[tid] = s; ss2[tid] = s2;
    __syncthreads();
    if (tid < 128) { ss[tid] += ss[tid + 128]; ss2[tid] += ss2[tid + 128]; }
    __syncthreads();
    if (tid < 64) { ss[tid] += ss[tid + 64]; ss2[tid] += ss2[tid + 64]; }
    __syncthreads();
    if (tid < 32) {
        float a = ss[tid] + ss[tid + 32];
        float b = ss2[tid] + ss2[tid + 32];
        atomicAdd(&g_stats[f], a);
        atomicAdd(&g_stats[HID + f], b);
    }
}

// ---------------- BN normalize + ReLU ----------------
__global__ __launch_bounds__(256) void bn_norm_relu_kernel(
    const float* __restrict__ Y, const float* __restrict__ gamma,
    const float* __restrict__ beta, float* __restrict__ X)
{
    int i4 = blockIdx.x * 256 + threadIdx.x;      // grid = K_CB*HID/4/256 = 4096
    int f0 = (i4 * 4) & (HID - 1);
    float4 y = ((const float4*)Y)[i4];
    float yv[4] = { y.x, y.y, y.z, y.w };
    float out[4];
#pragma unroll
    for (int j = 0; j < 4; j++) {
        int f = f0 + j;
        float m = g_stats[f] * (1.f / K_CB);
        float var = g_stats[HID + f] * (1.f / K_CB) - m * m;
        float o = (yv[j] - m) * rsqrtf(var + EPS_BN) * gamma[f] + beta[f];
        out[j] = fmaxf(o, 0.f);
    }
    ((float4*)X)[i4] = make_float4(out[0], out[1], out[2], out[3]);
}

// ---------------- embed L2 norm + ||e||^2 ----------------
__global__ __launch_bounds__(256) void embed_norm_kernel(const float* __restrict__ Eraw)
{
    int row = blockIdx.x * 8 + (threadIdx.x >> 5);   // grid = K_CB/8 = 512
    int lane = threadIdx.x & 31;
    float v0 = Eraw[row * VQd + lane];
    float v1 = Eraw[row * VQd + 32 + lane];
    float s = v0 * v0 + v1 * v1;
#pragma unroll
    for (int off = 16; off; off >>= 1) s += __shfl_xor_sync(0xffffffffu, s, off);
    float norm = sqrtf(s);
    float sc = 1.f / (norm + EPS_N);
    g_embed[row * VQd + lane] = v0 * sc;
    g_embed[row * VQd + 32 + lane] = v1 * sc;
    if (lane == 0) g_enorm2[row] = s * sc * sc;
}

// ---------------- hidden projection: h[b,t,v] = sum_d h_in[b,d,t]*Pw[v,d] + Pb[v]; L2-normalize ----------------
__global__ __launch_bounds__(256) void hproj_kernel(
    const float* __restrict__ Hin, const float* __restrict__ Pw,
    const float* __restrict__ Pb, float* __restrict__ Hout)
{
    __shared__ float Ash[32][132];   // [d][t], 128 t
    __shared__ float Wsh[32][65];    // [d][v], 64 v
    const int tid = threadIdx.x;
    const int b = blockIdx.y;
    const int t0 = blockIdx.x * 128;
    const int tx = tid & 15, ty = tid >> 4;
    float acc[8][4];
#pragma unroll
    for (int i = 0; i < 8; i++)
#pragma unroll
        for (int j = 0; j < 4; j++) acc[i][j] = 0.f;

    const int lt = tid & 127;
    const int ldr = tid >> 7;     // 0..1
    const int wv = tid >> 5;      // 0..7
    const int wd = tid & 31;

    for (int d0 = 0; d0 < Dd; d0 += 32) {
#pragma unroll
        for (int dd = ldr; dd < 32; dd += 2)
            Ash[dd][lt] = Hin[(size_t)(b * Dd + d0 + dd) * Tt + t0 + lt];
#pragma unroll
        for (int vv = wv; vv < 64; vv += 8)
            Wsh[wd][vv] = Pw[vv * Dd + d0 + wd];
        __syncthreads();
#pragma unroll
        for (int kk = 0; kk < 32; kk++) {
            float ar[8], br[4];
            *(float4*)&ar[0] = *(const float4*)&Ash[kk][ty * 4];
            *(float4*)&ar[4] = *(const float4*)&Ash[kk][64 + ty * 4];
#pragma unroll
            for (int j = 0; j < 4; j++) br[j] = Wsh[kk][tx * 4 + j];
#pragma unroll
            for (int i = 0; i < 8; i++)
#pragma unroll
                for (int j = 0; j < 4; j++)
                    acc[i][j] = fmaf(ar[i], br[j], acc[i][j]);
        }
        __syncthreads();
    }
    float bb[4];
#pragma unroll
    for (int j = 0; j < 4; j++) bb[j] = Pb[tx * 4 + j];
#pragma unroll
    for (int i = 0; i < 8; i++) {
        float hv[4]; float ssq = 0.f;
#pragma unroll
        for (int j = 0; j < 4; j++) { hv[j] = acc[i][j] + bb[j]; ssq += hv[j] * hv[j]; }
#pragma unroll
        for (int off = 8; off; off >>= 1) ssq += __shfl_xor_sync(0xffffffffu, ssq, off, 16);
        float sc = 1.f / (sqrtf(ssq) + EPS_N);
        int t = t0 + ((i < 4) ? ty * 4 + i : 64 + ty * 4 + (i - 4));
        float4 o = make_float4(hv[0] * sc, hv[1] * sc, hv[2] * sc, hv[3] * sc);
        *(float4*)&Hout[(size_t)(b * Tt + t) * VQd + tx * 4] = o;
    }
}

// ---------------- score GEMM + fused argmax ----------------
// score = 2*h.e - ||e||^2 ; argmax over codes == argmax(-d). Tie-break: smallest index
// (packed as 0xFFFFFFFF - idx so larger key wins ties with smaller index).
__global__ __launch_bounds__(256, 2) void score_argmax_kernel()
{
    __shared__ float As[8][132];
    __shared__ float Bs[8][132];
    const int tid = threadIdx.x;
    const int tx = tid & 15, ty = tid >> 4;
    const int m0 = blockIdx.y * 128, n0 = blockIdx.x * 128;
    const int lr = tid >> 1;
    const int lc = (tid & 1) << 2;
    const float* Ag = g_h + (size_t)(m0 + lr) * VQd + lc;
    const float* Bg = g_embed + (size_t)(n0 + lr) * VQd + lc;
    float acc[8][8];
#pragma unroll
    for (int i = 0; i < 8; i++)
#pragma unroll
        for (int j = 0; j < 8; j++) acc[i][j] = 0.f;

    for (int k0 = 0; k0 < VQd; k0 += 8) {
        float4 a4 = *(const float4*)(Ag + k0);
        float4 b4 = *(const float4*)(Bg + k0);
        As[lc + 0][lr] = a4.x; As[lc + 1][lr] = a4.y; As[lc + 2][lr] = a4.z; As[lc + 3][lr] = a4.w;
        Bs[lc + 0][lr] = b4.x; Bs[lc + 1][lr] = b4.y; Bs[lc + 2][lr] = b4.z; Bs[lc + 3][lr] = b4.w;
        __syncthreads();
#pragma unroll
        for (int kk = 0; kk < 8; kk++) {
            float ar[8], br[8];
            *(float4*)&ar[0] = *(const float4*)&As[kk][ty * 4];
            *(float4*)&ar[4] = *(const float4*)&As[kk][64 + ty * 4];
            *(float4*)&br[0] = *(const float4*)&Bs[kk][tx * 4];
            *(float4*)&br[4] = *(const float4*)&Bs[kk][64 + tx * 4];
#pragma unroll
            for (int i = 0; i < 8; i++)
#pragma unroll
                for (int j = 0; j < 8; j++)
                    acc[i][j] = fmaf(ar[i], br[j], acc[i][j]);
        }
        __syncthreads();
    }
#pragma unroll
    for (int i = 0; i < 8; i++) {
        int row = m0 + ((i < 4) ? ty * 4 + i : 64 + ty * 4 + (i - 4));
        unsigned long long best = 0ull;
#pragma unroll
        for (int j = 0; j < 8; j++) {
            int col = n0 + ((j < 4) ? tx * 4 + j : 64 + tx * 4 + (j - 4));
            float s = 2.f * acc[i][j] - g_enorm2[col];
            unsigned u = __float_as_uint(s);
            u = (u & 0x80000000u) ? ~u : (u | 0x80000000u);
            unsigned long long key =
                ((unsigned long long)u << 32) | (unsigned)(0xFFFFFFFFu - (unsigned)col);
            best = (key > best) ? key : best;
        }
#pragma unroll
        for (int off = 8; off; off >>= 1) {
            unsigned long long o = __shfl_xor_sync(0xffffffffu, best, off, 16);
            best = (o > best) ? o : best;
        }
        if (tx == 0) atomicMax(&g_best[row], best);
    }
}

// ---------------- gather masked codebook rows + emit codes ----------------
__global__ __launch_bounds__(256) void gather_kernel(
    const int* __restrict__ attn, float* __restrict__ out_codes, int write_codes)
{
    int idx = blockIdx.x * 256 + threadIdx.x;    // grid = NTOK*16/256 = 1024
    int bt = idx >> 4;
    int v = (idx & 15) << 2;
    unsigned long long key = g_best[bt];
    int code = (int)(0xFFFFFFFFu - (unsigned)(key & 0xFFFFFFFFull));
    int msk = (attn[bt] == 1);
    float4 e = msk ? *(const float4*)&g_embed[(size_t)code * VQd + v]
                   : make_float4(0.f, 0.f, 0.f, 0.f);
    *(float4*)&g_esel[(size_t)bt * VQd + v] = e;
    if (write_codes && (idx & 15) == 0)
        out_codes[bt] = msk ? (float)code : 0.f;
}

// ---------------- host launcher ----------------
extern "C" void kernel_launch(void* const* d_in, const int* in_sizes, int n_in,
                              void* d_out, int out_size)
{
    const float* h_in     = (const float*)d_in[0];
    const int*   attn     = (const int*)  d_in[1];
    const float* proj_w   = (const float*)d_in[2];
    const float* proj_b   = (const float*)d_in[3];
    const float* inv_w    = (const float*)d_in[4];
    const float* inv_b    = (const float*)d_in[5];
    const float* mlp_w_in = (const float*)d_in[6];
    const float* mlp_b_in = (const float*)d_in[7];
    const float* w_mid    = (const float*)d_in[8];
    const float* b_mid    = (const float*)d_in[9];
    const float* w_out    = (const float*)d_in[10];
    const float* b_out    = (const float*)d_in[11];
    const float* gamma    = (const float*)d_in[12];
    const float* beta     = (const float*)d_in[13];
    float* out = (float*)d_out;

    void *px_, *py_, *pes_, *ph_;
    cudaGetSymbolAddress(&px_, g_x);
    cudaGetSymbolAddress(&py_, g_y);
    cudaGetSymbolAddress(&pes_, g_esel);
    cudaGetSymbolAddress(&ph_, g_h);
    float* px = (float*)px_;
    float* py = (float*)py_;
    float* pes = (float*)pes_;
    float* ph = (float*)ph_;

    // 1) codebook MLP
    layer0_kernel<<<dim3(4, 256), 256>>>(mlp_w_in, mlp_b_in, gamma, beta, px);
    for (int i = 0; i < N_MID; i++) {
        gemm128_nt<<<dim3(HID / 128, K_CB / 128), 256>>>(
            px, w_mid + (size_t)i * HID * HID, b_mid + i * HID, py, K_CB, HID, HID);
        zero_stats_kernel<<<8, 256>>>();
        bn_stats_kernel<<<dim3(HID / 32, K_CB / 128), 256>>>(py);
        bn_norm_relu_kernel<<<(K_CB * HID / 4) / 256, 256>>>(
            py, gamma + (i + 1) * HID, beta + (i + 1) * HID, px);
    }
    gemm64_nt<<<dim3(1, K_CB / 64), 256>>>(px, w_out, b_out, py, K_CB, VQd, HID);
    embed_norm_kernel<<<K_CB / 8, 256>>>(py);

    // 2) hidden projection + L2 normalize
    hproj_kernel<<<dim3(Tt / 128, Bb), 256>>>(h_in, proj_w, proj_b, ph);

    // 3) nearest-code argmax
    zero_best_kernel<<<NTOK / 256, 256>>>();
    score_argmax_kernel<<<dim3(K_CB / 128, NTOK / 128), 256>>>();

    // 4) masked gather + codes
    int write_codes = (out_size >= NTOK * Dd + NTOK) ? 1 : 0;
    gather_kernel<<<NTOK * 16 / 256, 256>>>(attn, out + (size_t)NTOK * Dd, write_codes);

    // 5) inverse projection straight into d_out
    gemm128_nt<<<dim3(Dd / 128, NTOK / 128), 256>>>(
        pes, inv_w, inv_b, out, NTOK, Dd, VQd);
}